// round 1
// baseline (speedup 1.0000x reference)
#include <cuda_runtime.h>
#include <cuda_bf16.h>
#include <math.h>

// ---------------- problem constants ----------------
#define BS      2
#define NQ      40000
#define NV      40000
#define EMBED   256
#define HEADS   8
#define POINTS  4
#define HEAD_DIM 32
#define SH      200
#define SW      200

#define MROWS   (BS * NQ)      // 80000, also BS*NV

// ---------------- device scratch (no allocs allowed) ----------------
__device__ float g_v   [(size_t)BS * NV * EMBED];            // projected value
__device__ float g_off [(size_t)BS * NQ * HEADS * POINTS * 2];
__device__ float g_attn[(size_t)BS * NQ * HEADS * POINTS];
__device__ float g_tmp [(size_t)BS * NQ * EMBED];            // sampled output pre-W_out

// ---------------- fp32 tiled GEMM: C = A[M,K] @ B[K,N] + bias (+res) ----------------
template<int BM, int BN, int BK, int TM, int TN, bool RES>
__global__ void __launch_bounds__((BM/TM)*(BN/TN))
sgemm_kernel(const float* __restrict__ A, const float* __restrict__ B,
             const float* __restrict__ bias, const float* __restrict__ res,
             float* __restrict__ C, int M, int N, int K)
{
    constexpr int THREADS = (BM/TM)*(BN/TN);
    __shared__ float As[BK][BM];
    __shared__ float Bsm[BK][BN];

    const int tid = threadIdx.x;
    const int bm  = blockIdx.y;
    const int bn  = blockIdx.x;
    const int tr  = tid / (BN/TN);
    const int tc  = tid % (BN/TN);

    float acc[TM][TN];
#pragma unroll
    for (int i = 0; i < TM; i++)
#pragma unroll
        for (int j = 0; j < TN; j++) acc[i][j] = 0.f;

    const float* Ab = A + (size_t)bm * BM * K;
    const float* Bb = B + (size_t)bn * BN;

    for (int k0 = 0; k0 < K; k0 += BK) {
        // load A tile (transposed into As[k][m])
#pragma unroll
        for (int i = tid; i < BM * BK; i += THREADS) {
            int r = i / BK, c = i % BK;
            As[c][r] = Ab[(size_t)r * K + k0 + c];
        }
        // load B tile
#pragma unroll
        for (int i = tid; i < BK * BN; i += THREADS) {
            int r = i / BN, c = i % BN;
            Bsm[r][c] = Bb[(size_t)(k0 + r) * N + c];
        }
        __syncthreads();

#pragma unroll
        for (int k = 0; k < BK; k++) {
            float4 av = *reinterpret_cast<const float4*>(&As[k][tr * TM]);
            float4 bv = *reinterpret_cast<const float4*>(&Bsm[k][tc * TN]);
            float a[TM] = {av.x, av.y, av.z, av.w};
            float b[TN] = {bv.x, bv.y, bv.z, bv.w};
#pragma unroll
            for (int i = 0; i < TM; i++)
#pragma unroll
                for (int j = 0; j < TN; j++)
                    acc[i][j] = fmaf(a[i], b[j], acc[i][j]);
        }
        __syncthreads();
    }

    // epilogue
#pragma unroll
    for (int i = 0; i < TM; i++) {
        int row = bm * BM + tr * TM + i;
        int col = bn * BN + tc * TN;
        float4 bb = *reinterpret_cast<const float4*>(&bias[col]);
        float4 o;
        o.x = acc[i][0] + bb.x;
        o.y = acc[i][1] + bb.y;
        o.z = acc[i][2] + bb.z;
        o.w = acc[i][3] + bb.w;
        if (RES) {
            float4 rr = *reinterpret_cast<const float4*>(&res[(size_t)row * N + col]);
            o.x += rr.x; o.y += rr.y; o.z += rr.z; o.w += rr.w;
        }
        *reinterpret_cast<float4*>(&C[(size_t)row * N + col]) = o;
    }
}

// ---------------- sampling: softmax(attn) + bilinear gather + weighted sum ----------------
// One warp per (b, q, head); lane = head-dim channel. One block = one (b,q), 8 warps = 8 heads.
__global__ void __launch_bounds__(256)
sample_kernel(const float* __restrict__ refp, float* __restrict__ outp)
{
    const int lane = threadIdx.x & 31;
    const int h    = threadIdx.x >> 5;        // 8 warps -> 8 heads
    const int bq   = blockIdx.x;              // 0 .. BS*NQ-1
    const int b    = bq / NQ;

    const float rx = refp[(size_t)bq * 2 + 0];
    const float ry = refp[(size_t)bq * 2 + 1];

    const float* offp = g_off  + ((size_t)bq * HEADS + h) * POINTS * 2;
    const float* awp  = g_attn + ((size_t)bq * HEADS + h) * POINTS;

    // softmax over the 4 points (redundant across lanes; cheap)
    float araw[POINTS], e[POINTS];
    float m = -1e30f;
#pragma unroll
    for (int p = 0; p < POINTS; p++) { araw[p] = awp[p]; m = fmaxf(m, araw[p]); }
    float s = 0.f;
#pragma unroll
    for (int p = 0; p < POINTS; p++) { e[p] = __expf(araw[p] - m); s += e[p]; }
    const float inv = 1.f / s;

    const float* vbase = g_v + (size_t)b * NV * EMBED + h * HEAD_DIM + lane;

    float acc = 0.f;
#pragma unroll
    for (int p = 0; p < POINTS; p++) {
        // replicate reference arithmetic exactly
        float locx = rx + offp[2 * p + 0] * (1.f / (float)SW);
        float locy = ry + offp[2 * p + 1] * (1.f / (float)SH);
        float gx = 2.f * locx - 1.f;
        float gy = 2.f * locy - 1.f;
        float px = ((gx + 1.f) * (float)SW - 1.f) * 0.5f;
        float py = ((gy + 1.f) * (float)SH - 1.f) * 0.5f;

        float x0f = floorf(px), y0f = floorf(py);
        int   x0 = (int)x0f,    y0 = (int)y0f;
        float fx = px - x0f,    fy = py - y0f;

        float w00 = (1.f - fx) * (1.f - fy);
        float w01 = fx * (1.f - fy);
        float w10 = (1.f - fx) * fy;
        float w11 = fx * fy;

        const bool xv0 = (x0 >= 0)     && (x0 <= SW - 1);
        const bool xv1 = (x0 + 1 >= 0) && (x0 + 1 <= SW - 1);
        const bool yv0 = (y0 >= 0)     && (y0 <= SH - 1);
        const bool yv1 = (y0 + 1 >= 0) && (y0 + 1 <= SH - 1);

        float sum = 0.f;
        if (yv0) {
            const size_t rowoff = (size_t)(y0 * SW) * EMBED;
            if (xv0) sum = fmaf(w00, vbase[rowoff + (size_t)x0 * EMBED], sum);
            if (xv1) sum = fmaf(w01, vbase[rowoff + (size_t)(x0 + 1) * EMBED], sum);
        }
        if (yv1) {
            const size_t rowoff = (size_t)((y0 + 1) * SW) * EMBED;
            if (xv0) sum = fmaf(w10, vbase[rowoff + (size_t)x0 * EMBED], sum);
            if (xv1) sum = fmaf(w11, vbase[rowoff + (size_t)(x0 + 1) * EMBED], sum);
        }
        acc = fmaf(e[p] * inv, sum, acc);
    }

    outp[(size_t)bq * EMBED + h * HEAD_DIM + lane] = acc;
}

// ---------------- launch ----------------
extern "C" void kernel_launch(void* const* d_in, const int* in_sizes, int n_in,
                              void* d_out, int out_size)
{
    const float* query   = (const float*)d_in[0];
    const float* value   = (const float*)d_in[1];
    const float* refpts  = (const float*)d_in[2];
    // d_in[3] = spatial_shapes (compile-time constants)
    const float* W_value = (const float*)d_in[4];
    const float* b_value = (const float*)d_in[5];
    const float* W_off   = (const float*)d_in[6];
    const float* b_off   = (const float*)d_in[7];
    const float* W_attn  = (const float*)d_in[8];
    const float* b_attn  = (const float*)d_in[9];
    const float* W_out   = (const float*)d_in[10];
    const float* b_out   = (const float*)d_in[11];
    float* out = (float*)d_out;

    float *pv, *poff, *pattn, *ptmp;
    cudaGetSymbolAddress((void**)&pv,    g_v);
    cudaGetSymbolAddress((void**)&poff,  g_off);
    cudaGetSymbolAddress((void**)&pattn, g_attn);
    cudaGetSymbolAddress((void**)&ptmp,  g_tmp);

    // 1) v = value @ W_value + b_value      [80000 x 256]
    {
        dim3 grid(EMBED / 64, MROWS / 64);
        sgemm_kernel<64, 64, 16, 4, 4, false><<<grid, 256>>>(
            value, W_value, b_value, nullptr, pv, MROWS, EMBED, EMBED);
    }
    // 2) off = query @ W_off + b_off        [80000 x 64]
    {
        dim3 grid(1, MROWS / 64);
        sgemm_kernel<64, 64, 16, 4, 4, false><<<grid, 256>>>(
            query, W_off, b_off, nullptr, poff, MROWS, 64, EMBED);
    }
    // 3) attn = query @ W_attn + b_attn     [80000 x 32]
    {
        dim3 grid(1, MROWS / 64);
        sgemm_kernel<64, 32, 16, 4, 4, false><<<grid, 128>>>(
            query, W_attn, b_attn, nullptr, pattn, MROWS, 32, EMBED);
    }
    // 4) softmax + bilinear sample + weighted sum -> g_tmp
    {
        sample_kernel<<<BS * NQ, 256>>>(refpts, ptmp);
    }
    // 5) out = g_tmp @ W_out + b_out + query
    {
        dim3 grid(EMBED / 64, MROWS / 64);
        sgemm_kernel<64, 64, 16, 4, 4, true><<<grid, 256>>>(
            ptmp, W_out, b_out, query, out, MROWS, EMBED, EMBED);
    }
}

// round 3
// speedup vs baseline: 1.9642x; 1.9642x over previous
#include <cuda_runtime.h>
#include <cuda_bf16.h>
#include <math.h>
#include <stdint.h>

// ---------------- problem constants ----------------
#define BS      2
#define NQ      40000
#define NV      40000
#define EMBED   256
#define HEADS   8
#define POINTS  4
#define HEAD_DIM 32
#define SH      200
#define SW      200
#define MROWS   (BS * NQ)      // 80000

// ---------------- device scratch ----------------
__device__ float g_v   [(size_t)BS * NV * EMBED];
__device__ float g_off [(size_t)BS * NQ * HEADS * POINTS * 2];
__device__ float g_attn[(size_t)BS * NQ * HEADS * POINTS];
__device__ float g_tmp [(size_t)BS * NQ * EMBED];
// transposed + split weights: [N][K] bf16
__device__ __nv_bfloat16 g_Wv_hi [256 * 256], g_Wv_lo [256 * 256];
__device__ __nv_bfloat16 g_Wo_hi [256 * 256], g_Wo_lo [256 * 256];
__device__ __nv_bfloat16 g_Wof_hi[ 64 * 256], g_Wof_lo[ 64 * 256];
__device__ __nv_bfloat16 g_Wa_hi [ 32 * 256], g_Wa_lo [ 32 * 256];

// ---------------- warp mma helper ----------------
__device__ __forceinline__ void mma_bf16(float* d, const uint32_t* a, const uint32_t* b) {
    asm volatile(
        "mma.sync.aligned.m16n8k16.row.col.f32.bf16.bf16.f32 "
        "{%0,%1,%2,%3}, {%4,%5,%6,%7}, {%8,%9}, {%0,%1,%2,%3};"
        : "+f"(d[0]), "+f"(d[1]), "+f"(d[2]), "+f"(d[3])
        : "r"(a[0]), "r"(a[1]), "r"(a[2]), "r"(a[3]), "r"(b[0]), "r"(b[1]));
}

// ---------------- weight transpose + bf16 split ----------------
__global__ void convert_w_kernel(const float* __restrict__ W,
                                 __nv_bfloat16* __restrict__ hi,
                                 __nv_bfloat16* __restrict__ lo, int N)
{
    int idx = blockIdx.x * 256 + threadIdx.x;
    if (idx >= N * 256) return;
    int n = idx >> 8, k = idx & 255;
    float v = W[k * N + n];
    __nv_bfloat16 h = __float2bfloat16(v);
    hi[idx] = h;
    lo[idx] = __float2bfloat16(v - __bfloat162float(h));
}

// ---------------- split-bf16 HMMA GEMM: C[M,NT] = A[M,256] @ W[256,NT] + bias (+res) ----
// CTA: 128 rows x NT cols, 8 warps. K in 4 chunks of 64 via SMEM (stride 144B, pad).
template<int NT, bool RES>
__global__ void __launch_bounds__(256, 1)
mma_gemm_kernel(const float* __restrict__ A,
                const __nv_bfloat16* __restrict__ Bt_hi,
                const __nv_bfloat16* __restrict__ Bt_lo,
                const float* __restrict__ bias,
                const float* __restrict__ res,
                float* __restrict__ C)
{
    constexpr int K = 256, BK = 64, BM = 128;
    constexpr int WM  = (NT == 256) ? 2 : (NT == 64) ? 4 : 8;
    constexpr int WN  = 8 / WM;
    constexpr int WTM = BM / WM;           // rows per warp
    constexpr int WTN = NT / WN;           // cols per warp
    constexpr int MT  = WTM / 16;          // 16-row mma tiles
    constexpr int NTI = WTN / 8;           // 8-col mma tiles
    constexpr int AST = 144;               // bytes per 64-bf16 row (128 + 16 pad)
    constexpr int A_H = 0;
    constexpr int A_L = BM * AST;
    constexpr int B_H = 2 * BM * AST;
    constexpr int B_L = B_H + NT * AST;

    extern __shared__ char sm[];

    const int tid  = threadIdx.x;
    const int wid  = tid >> 5;
    const int lane = tid & 31;
    const int g    = lane >> 2;       // group id (row/col within tile)
    const int c    = lane & 3;        // thread in group (k-pair)
    const int wm   = wid / WN;
    const int wn   = wid % WN;
    const int wmBase = wm * WTM;
    const int wnBase = wn * WTN;
    const int bm   = blockIdx.x;

    float acc[MT][NTI][4];
#pragma unroll
    for (int i = 0; i < MT; i++)
#pragma unroll
        for (int j = 0; j < NTI; j++)
#pragma unroll
            for (int q = 0; q < 4; q++) acc[i][j][q] = 0.f;

    const int aFragBase = A_H + (wmBase + g) * AST + c * 4;
    const int bFragBase = B_H + (wnBase + g) * AST + c * 4;

    for (int it = 0; it < K / BK; it++) {
        const int k0 = it * BK;
        // ---- fill A tile: 128 rows x 64 fp32 -> bf16 hi/lo, padded rows ----
#pragma unroll
        for (int f = tid; f < BM * 32; f += 256) {
            const int r = f >> 5, c2 = f & 31;
            float2 a = *reinterpret_cast<const float2*>(
                &A[(size_t)(bm * BM + r) * K + k0 + c2 * 2]);
            __nv_bfloat16 h0 = __float2bfloat16(a.x);
            __nv_bfloat16 h1 = __float2bfloat16(a.y);
            __nv_bfloat16 l0 = __float2bfloat16(a.x - __bfloat162float(h0));
            __nv_bfloat16 l1 = __float2bfloat16(a.y - __bfloat162float(h1));
            __nv_bfloat162 vh; vh.x = h0; vh.y = h1;
            __nv_bfloat162 vl; vl.x = l0; vl.y = l1;
            *reinterpret_cast<__nv_bfloat162*>(sm + A_H + r * AST + c2 * 4) = vh;
            *reinterpret_cast<__nv_bfloat162*>(sm + A_L + r * AST + c2 * 4) = vl;
        }
        // ---- fill B tile: NT rows x 64 bf16 (pre-split) ----
#pragma unroll
        for (int f = tid; f < NT * 32; f += 256) {
            const int n = f >> 5, cu = f & 31;
            uint32_t hi = *reinterpret_cast<const uint32_t*>(&Bt_hi[n * K + k0 + cu * 2]);
            uint32_t lo = *reinterpret_cast<const uint32_t*>(&Bt_lo[n * K + k0 + cu * 2]);
            *reinterpret_cast<uint32_t*>(sm + B_H + n * AST + cu * 4) = hi;
            *reinterpret_cast<uint32_t*>(sm + B_L + n * AST + cu * 4) = lo;
        }
        __syncthreads();

#pragma unroll
        for (int ks = 0; ks < BK / 16; ks++) {
            const int kb = ks * 32;  // byte offset of this k16 within row
            uint32_t ah[MT][4], al[MT][4], bh[NTI][2];
            // B hi fragments
#pragma unroll
            for (int ni = 0; ni < NTI; ni++) {
                const int b0 = bFragBase + ni * 8 * AST + kb;
                bh[ni][0] = *reinterpret_cast<const uint32_t*>(sm + b0);
                bh[ni][1] = *reinterpret_cast<const uint32_t*>(sm + b0 + 16);
            }
            // A hi fragments
#pragma unroll
            for (int mi = 0; mi < MT; mi++) {
                const int a0 = aFragBase + mi * 16 * AST + kb;
                ah[mi][0] = *reinterpret_cast<const uint32_t*>(sm + a0);
                ah[mi][1] = *reinterpret_cast<const uint32_t*>(sm + a0 + 8 * AST);
                ah[mi][2] = *reinterpret_cast<const uint32_t*>(sm + a0 + 16);
                ah[mi][3] = *reinterpret_cast<const uint32_t*>(sm + a0 + 8 * AST + 16);
            }
            // pass 1: Ah x Bh
#pragma unroll
            for (int mi = 0; mi < MT; mi++)
#pragma unroll
                for (int ni = 0; ni < NTI; ni++)
                    mma_bf16(acc[mi][ni], ah[mi], bh[ni]);
            // A lo fragments, pass 2: Al x Bh
#pragma unroll
            for (int mi = 0; mi < MT; mi++) {
                const int a0 = (A_L - A_H) + aFragBase + mi * 16 * AST + kb;
                al[mi][0] = *reinterpret_cast<const uint32_t*>(sm + a0);
                al[mi][1] = *reinterpret_cast<const uint32_t*>(sm + a0 + 8 * AST);
                al[mi][2] = *reinterpret_cast<const uint32_t*>(sm + a0 + 16);
                al[mi][3] = *reinterpret_cast<const uint32_t*>(sm + a0 + 8 * AST + 16);
            }
#pragma unroll
            for (int mi = 0; mi < MT; mi++)
#pragma unroll
                for (int ni = 0; ni < NTI; ni++)
                    mma_bf16(acc[mi][ni], al[mi], bh[ni]);
            // B lo fragments, pass 3: Ah x Bl
            uint32_t bl[NTI][2];
#pragma unroll
            for (int ni = 0; ni < NTI; ni++) {
                const int b0 = (B_L - B_H) + bFragBase + ni * 8 * AST + kb;
                bl[ni][0] = *reinterpret_cast<const uint32_t*>(sm + b0);
                bl[ni][1] = *reinterpret_cast<const uint32_t*>(sm + b0 + 16);
            }
#pragma unroll
            for (int mi = 0; mi < MT; mi++)
#pragma unroll
                for (int ni = 0; ni < NTI; ni++)
                    mma_bf16(acc[mi][ni], ah[mi], bl[ni]);
        }
        __syncthreads();
    }

    // ---- epilogue ----
#pragma unroll
    for (int mi = 0; mi < MT; mi++) {
        const int row0 = bm * BM + wmBase + mi * 16 + g;
#pragma unroll
        for (int ni = 0; ni < NTI; ni++) {
            const int col = wnBase + ni * 8 + c * 2;
            float2 bb = *reinterpret_cast<const float2*>(&bias[col]);
            float2 o0, o1;
            o0.x = acc[mi][ni][0] + bb.x;
            o0.y = acc[mi][ni][1] + bb.y;
            o1.x = acc[mi][ni][2] + bb.x;
            o1.y = acc[mi][ni][3] + bb.y;
            if (RES) {
                float2 r0 = *reinterpret_cast<const float2*>(&res[(size_t)row0 * NT + col]);
                float2 r1 = *reinterpret_cast<const float2*>(&res[(size_t)(row0 + 8) * NT + col]);
                o0.x += r0.x; o0.y += r0.y;
                o1.x += r1.x; o1.y += r1.y;
            }
            *reinterpret_cast<float2*>(&C[(size_t)row0 * NT + col]) = o0;
            *reinterpret_cast<float2*>(&C[(size_t)(row0 + 8) * NT + col]) = o1;
        }
    }
}

// ---------------- sampling: softmax + bilinear gather + weighted sum ----------------
__global__ void __launch_bounds__(256)
sample_kernel(const float* __restrict__ refp, float* __restrict__ outp)
{
    const int lane = threadIdx.x & 31;
    const int h    = threadIdx.x >> 5;
    const int bq   = blockIdx.x;
    const int b    = bq / NQ;

    const float rx = refp[(size_t)bq * 2 + 0];
    const float ry = refp[(size_t)bq * 2 + 1];

    const float* offp = g_off  + ((size_t)bq * HEADS + h) * POINTS * 2;
    const float* awp  = g_attn + ((size_t)bq * HEADS + h) * POINTS;

    float araw[POINTS], e[POINTS];
    float m = -1e30f;
#pragma unroll
    for (int p = 0; p < POINTS; p++) { araw[p] = awp[p]; m = fmaxf(m, araw[p]); }
    float s = 0.f;
#pragma unroll
    for (int p = 0; p < POINTS; p++) { e[p] = __expf(araw[p] - m); s += e[p]; }
    const float inv = 1.f / s;

    const float* vbase = g_v + (size_t)b * NV * EMBED + h * HEAD_DIM + lane;

    float acc = 0.f;
#pragma unroll
    for (int p = 0; p < POINTS; p++) {
        float locx = rx + offp[2 * p + 0] * (1.f / (float)SW);
        float locy = ry + offp[2 * p + 1] * (1.f / (float)SH);
        float gx = 2.f * locx - 1.f;
        float gy = 2.f * locy - 1.f;
        float px = ((gx + 1.f) * (float)SW - 1.f) * 0.5f;
        float py = ((gy + 1.f) * (float)SH - 1.f) * 0.5f;

        float x0f = floorf(px), y0f = floorf(py);
        int   x0 = (int)x0f,    y0 = (int)y0f;
        float fx = px - x0f,    fy = py - y0f;

        float w00 = (1.f - fx) * (1.f - fy);
        float w01 = fx * (1.f - fy);
        float w10 = (1.f - fx) * fy;
        float w11 = fx * fy;

        const bool xv0 = (x0 >= 0)     && (x0 <= SW - 1);
        const bool xv1 = (x0 + 1 >= 0) && (x0 + 1 <= SW - 1);
        const bool yv0 = (y0 >= 0)     && (y0 <= SH - 1);
        const bool yv1 = (y0 + 1 >= 0) && (y0 + 1 <= SH - 1);

        float sum = 0.f;
        if (yv0) {
            const size_t rowoff = (size_t)(y0 * SW) * EMBED;
            if (xv0) sum = fmaf(w00, vbase[rowoff + (size_t)x0 * EMBED], sum);
            if (xv1) sum = fmaf(w01, vbase[rowoff + (size_t)(x0 + 1) * EMBED], sum);
        }
        if (yv1) {
            const size_t rowoff = (size_t)((y0 + 1) * SW) * EMBED;
            if (xv0) sum = fmaf(w10, vbase[rowoff + (size_t)x0 * EMBED], sum);
            if (xv1) sum = fmaf(w11, vbase[rowoff + (size_t)(x0 + 1) * EMBED], sum);
        }
        acc = fmaf(e[p] * inv, sum, acc);
    }

    outp[(size_t)bq * EMBED + h * HEAD_DIM + lane] = acc;
}

// ---------------- launch ----------------
extern "C" void kernel_launch(void* const* d_in, const int* in_sizes, int n_in,
                              void* d_out, int out_size)
{
    const float* query   = (const float*)d_in[0];
    const float* value   = (const float*)d_in[1];
    const float* refpts  = (const float*)d_in[2];
    const float* W_value = (const float*)d_in[4];
    const float* b_value = (const float*)d_in[5];
    const float* W_off   = (const float*)d_in[6];
    const float* b_off   = (const float*)d_in[7];
    const float* W_attn  = (const float*)d_in[8];
    const float* b_attn  = (const float*)d_in[9];
    const float* W_out   = (const float*)d_in[10];
    const float* b_out   = (const float*)d_in[11];
    float* out = (float*)d_out;

    float *pv, *poff, *pattn, *ptmp;
    __nv_bfloat16 *wv_h, *wv_l, *wo_h, *wo_l, *wof_h, *wof_l, *wa_h, *wa_l;
    cudaGetSymbolAddress((void**)&pv,    g_v);
    cudaGetSymbolAddress((void**)&poff,  g_off);
    cudaGetSymbolAddress((void**)&pattn, g_attn);
    cudaGetSymbolAddress((void**)&ptmp,  g_tmp);
    cudaGetSymbolAddress((void**)&wv_h,  g_Wv_hi);  cudaGetSymbolAddress((void**)&wv_l,  g_Wv_lo);
    cudaGetSymbolAddress((void**)&wo_h,  g_Wo_hi);  cudaGetSymbolAddress((void**)&wo_l,  g_Wo_lo);
    cudaGetSymbolAddress((void**)&wof_h, g_Wof_hi); cudaGetSymbolAddress((void**)&wof_l, g_Wof_lo);
    cudaGetSymbolAddress((void**)&wa_h,  g_Wa_hi);  cudaGetSymbolAddress((void**)&wa_l,  g_Wa_lo);

    const int SMEM_256 = 2 * 128 * 144 + 2 * 256 * 144; // 110592
    const int SMEM_64  = 2 * 128 * 144 + 2 *  64 * 144; //  55296
    const int SMEM_32  = 2 * 128 * 144 + 2 *  32 * 144; //  46080
    cudaFuncSetAttribute(mma_gemm_kernel<256, false>, cudaFuncAttributeMaxDynamicSharedMemorySize, SMEM_256);
    cudaFuncSetAttribute(mma_gemm_kernel<256, true >, cudaFuncAttributeMaxDynamicSharedMemorySize, SMEM_256);
    cudaFuncSetAttribute(mma_gemm_kernel< 64, false>, cudaFuncAttributeMaxDynamicSharedMemorySize, SMEM_64);
    cudaFuncSetAttribute(mma_gemm_kernel< 32, false>, cudaFuncAttributeMaxDynamicSharedMemorySize, SMEM_32);

    // weight transpose + bf16 split
    convert_w_kernel<<<(256 * 256 + 255) / 256, 256>>>(W_value, wv_h,  wv_l,  256);
    convert_w_kernel<<<(256 * 256 + 255) / 256, 256>>>(W_out,   wo_h,  wo_l,  256);
    convert_w_kernel<<<( 64 * 256 + 255) / 256, 256>>>(W_off,   wof_h, wof_l,  64);
    convert_w_kernel<<<( 32 * 256 + 255) / 256, 256>>>(W_attn,  wa_h,  wa_l,   32);

    const int GRID = MROWS / 128; // 625

    // 1) v = value @ W_value + b_value
    mma_gemm_kernel<256, false><<<GRID, 256, SMEM_256>>>(value, wv_h, wv_l, b_value, nullptr, pv);
    // 2) off = query @ W_off + b_off
    mma_gemm_kernel<64, false><<<GRID, 256, SMEM_64>>>(query, wof_h, wof_l, b_off, nullptr, poff);
    // 3) attn = query @ W_attn + b_attn
    mma_gemm_kernel<32, false><<<GRID, 256, SMEM_32>>>(query, wa_h, wa_l, b_attn, nullptr, pattn);
    // 4) softmax + bilinear sample
    sample_kernel<<<BS * NQ, 256>>>(refpts, ptmp);
    // 5) out = tmp @ W_out + b_out + query
    mma_gemm_kernel<256, true><<<GRID, 256, SMEM_256>>>(ptmp, wo_h, wo_l, b_out, query, out);
}

// round 4
// speedup vs baseline: 2.3895x; 1.2165x over previous
#include <cuda_runtime.h>
#include <cuda_bf16.h>
#include <math.h>
#include <stdint.h>

// ---------------- problem constants ----------------
#define BS      2
#define NQ      40000
#define NV      40000
#define EMBED   256
#define HEADS   8
#define POINTS  4
#define HEAD_DIM 32
#define SH      200
#define SW      200
#define MROWS   (BS * NQ)      // 80000

// ---------------- device scratch ----------------
__device__ float g_v   [(size_t)BS * NV * EMBED];
__device__ float g_oa  [(size_t)BS * NQ * 96];     // fused [off(64) | attn(32)]
__device__ float g_tmp [(size_t)BS * NQ * EMBED];
__device__ float g_boa [96];
// transposed + split weights: [N][K] bf16
__device__ __nv_bfloat16 g_Wv_hi [256 * 256], g_Wv_lo [256 * 256];
__device__ __nv_bfloat16 g_Wo_hi [256 * 256], g_Wo_lo [256 * 256];
__device__ __nv_bfloat16 g_Woa_hi[ 96 * 256], g_Woa_lo[ 96 * 256];

// ---------------- warp mma helper ----------------
__device__ __forceinline__ void mma_bf16(float* d, const uint32_t* a, const uint32_t* b) {
    asm volatile(
        "mma.sync.aligned.m16n8k16.row.col.f32.bf16.bf16.f32 "
        "{%0,%1,%2,%3}, {%4,%5,%6,%7}, {%8,%9}, {%0,%1,%2,%3};"
        : "+f"(d[0]), "+f"(d[1]), "+f"(d[2]), "+f"(d[3])
        : "r"(a[0]), "r"(a[1]), "r"(a[2]), "r"(a[3]), "r"(b[0]), "r"(b[1]));
}

// ---------------- weight transpose + bf16 split ----------------
__global__ void convert_w_kernel(const float* __restrict__ W,
                                 __nv_bfloat16* __restrict__ hi,
                                 __nv_bfloat16* __restrict__ lo, int N)
{
    int idx = blockIdx.x * 256 + threadIdx.x;
    if (idx >= N * 256) return;
    int n = idx >> 8, k = idx & 255;
    float v = W[k * N + n];
    __nv_bfloat16 h = __float2bfloat16(v);
    hi[idx] = h;
    lo[idx] = __float2bfloat16(v - __bfloat162float(h));
}

// combined [W_off | W_attn] transpose+split, plus combined bias
__global__ void convert_oa_kernel(const float* __restrict__ Woff, const float* __restrict__ boff,
                                  const float* __restrict__ Wattn, const float* __restrict__ battn,
                                  __nv_bfloat16* __restrict__ hi, __nv_bfloat16* __restrict__ lo,
                                  float* __restrict__ bcomb)
{
    int idx = blockIdx.x * 256 + threadIdx.x;
    if (idx >= 96 * 256) return;
    int n = idx >> 8, k = idx & 255;
    float v = (n < 64) ? Woff[k * 64 + n] : Wattn[k * 32 + (n - 64)];
    __nv_bfloat16 h = __float2bfloat16(v);
    hi[idx] = h;
    lo[idx] = __float2bfloat16(v - __bfloat162float(h));
    if (idx < 96) bcomb[idx] = (idx < 64) ? boff[idx] : battn[idx - 64];
}

// ---------------- split-bf16 HMMA GEMM: C[M,NT] = A[M,256] @ W[256,NT] + bias (+res) ----
template<int NT, bool RES>
__global__ void __launch_bounds__(256, 1)
mma_gemm_kernel(const float* __restrict__ A,
                const __nv_bfloat16* __restrict__ Bt_hi,
                const __nv_bfloat16* __restrict__ Bt_lo,
                const float* __restrict__ bias,
                const float* __restrict__ res,
                float* __restrict__ C)
{
    constexpr int K = 256, BK = 64, BM = 128;
    constexpr int WM  = 2;
    constexpr int WN  = 4;
    constexpr int WTM = BM / WM;           // 64 rows per warp
    constexpr int WTN = NT / WN;           // cols per warp
    constexpr int MT  = WTM / 16;          // 4
    constexpr int NTI = WTN / 8;           // 8 (NT=256) or 3 (NT=96)
    constexpr int AST = 144;               // bytes per 64-bf16 row (128 + 16 pad)
    constexpr int A_H = 0;
    constexpr int A_L = BM * AST;
    constexpr int B_H = 2 * BM * AST;
    constexpr int B_L = B_H + NT * AST;

    extern __shared__ char sm[];

    const int tid  = threadIdx.x;
    const int wid  = tid >> 5;
    const int lane = tid & 31;
    const int g    = lane >> 2;
    const int c    = lane & 3;
    const int wm   = wid / WN;
    const int wn   = wid % WN;
    const int wmBase = wm * WTM;
    const int wnBase = wn * WTN;
    const int bm   = blockIdx.x;

    float acc[MT][NTI][4];
#pragma unroll
    for (int i = 0; i < MT; i++)
#pragma unroll
        for (int j = 0; j < NTI; j++)
#pragma unroll
            for (int q = 0; q < 4; q++) acc[i][j][q] = 0.f;

    const int aFragBase = A_H + (wmBase + g) * AST + c * 4;
    const int bFragBase = B_H + (wnBase + g) * AST + c * 4;

    for (int it = 0; it < K / BK; it++) {
        const int k0 = it * BK;
#pragma unroll
        for (int f = tid; f < BM * 32; f += 256) {
            const int r = f >> 5, c2 = f & 31;
            float2 a = *reinterpret_cast<const float2*>(
                &A[(size_t)(bm * BM + r) * K + k0 + c2 * 2]);
            __nv_bfloat16 h0 = __float2bfloat16(a.x);
            __nv_bfloat16 h1 = __float2bfloat16(a.y);
            __nv_bfloat16 l0 = __float2bfloat16(a.x - __bfloat162float(h0));
            __nv_bfloat16 l1 = __float2bfloat16(a.y - __bfloat162float(h1));
            __nv_bfloat162 vh; vh.x = h0; vh.y = h1;
            __nv_bfloat162 vl; vl.x = l0; vl.y = l1;
            *reinterpret_cast<__nv_bfloat162*>(sm + A_H + r * AST + c2 * 4) = vh;
            *reinterpret_cast<__nv_bfloat162*>(sm + A_L + r * AST + c2 * 4) = vl;
        }
#pragma unroll
        for (int f = tid; f < NT * 32; f += 256) {
            const int n = f >> 5, cu = f & 31;
            uint32_t hi = *reinterpret_cast<const uint32_t*>(&Bt_hi[n * K + k0 + cu * 2]);
            uint32_t lo = *reinterpret_cast<const uint32_t*>(&Bt_lo[n * K + k0 + cu * 2]);
            *reinterpret_cast<uint32_t*>(sm + B_H + n * AST + cu * 4) = hi;
            *reinterpret_cast<uint32_t*>(sm + B_L + n * AST + cu * 4) = lo;
        }
        __syncthreads();

#pragma unroll
        for (int ks = 0; ks < BK / 16; ks++) {
            const int kb = ks * 32;
            uint32_t ah[MT][4], al[MT][4], bh[NTI][2];
#pragma unroll
            for (int ni = 0; ni < NTI; ni++) {
                const int b0 = bFragBase + ni * 8 * AST + kb;
                bh[ni][0] = *reinterpret_cast<const uint32_t*>(sm + b0);
                bh[ni][1] = *reinterpret_cast<const uint32_t*>(sm + b0 + 16);
            }
#pragma unroll
            for (int mi = 0; mi < MT; mi++) {
                const int a0 = aFragBase + mi * 16 * AST + kb;
                ah[mi][0] = *reinterpret_cast<const uint32_t*>(sm + a0);
                ah[mi][1] = *reinterpret_cast<const uint32_t*>(sm + a0 + 8 * AST);
                ah[mi][2] = *reinterpret_cast<const uint32_t*>(sm + a0 + 16);
                ah[mi][3] = *reinterpret_cast<const uint32_t*>(sm + a0 + 8 * AST + 16);
            }
#pragma unroll
            for (int mi = 0; mi < MT; mi++)
#pragma unroll
                for (int ni = 0; ni < NTI; ni++)
                    mma_bf16(acc[mi][ni], ah[mi], bh[ni]);
#pragma unroll
            for (int mi = 0; mi < MT; mi++) {
                const int a0 = (A_L - A_H) + aFragBase + mi * 16 * AST + kb;
                al[mi][0] = *reinterpret_cast<const uint32_t*>(sm + a0);
                al[mi][1] = *reinterpret_cast<const uint32_t*>(sm + a0 + 8 * AST);
                al[mi][2] = *reinterpret_cast<const uint32_t*>(sm + a0 + 16);
                al[mi][3] = *reinterpret_cast<const uint32_t*>(sm + a0 + 8 * AST + 16);
            }
#pragma unroll
            for (int mi = 0; mi < MT; mi++)
#pragma unroll
                for (int ni = 0; ni < NTI; ni++)
                    mma_bf16(acc[mi][ni], al[mi], bh[ni]);
            uint32_t bl[NTI][2];
#pragma unroll
            for (int ni = 0; ni < NTI; ni++) {
                const int b0 = (B_L - B_H) + bFragBase + ni * 8 * AST + kb;
                bl[ni][0] = *reinterpret_cast<const uint32_t*>(sm + b0);
                bl[ni][1] = *reinterpret_cast<const uint32_t*>(sm + b0 + 16);
            }
#pragma unroll
            for (int mi = 0; mi < MT; mi++)
#pragma unroll
                for (int ni = 0; ni < NTI; ni++)
                    mma_bf16(acc[mi][ni], ah[mi], bl[ni]);
        }
        __syncthreads();
    }

#pragma unroll
    for (int mi = 0; mi < MT; mi++) {
        const int row0 = bm * BM + wmBase + mi * 16 + g;
#pragma unroll
        for (int ni = 0; ni < NTI; ni++) {
            const int col = wnBase + ni * 8 + c * 2;
            float2 bb = *reinterpret_cast<const float2*>(&bias[col]);
            float2 o0, o1;
            o0.x = acc[mi][ni][0] + bb.x;
            o0.y = acc[mi][ni][1] + bb.y;
            o1.x = acc[mi][ni][2] + bb.x;
            o1.y = acc[mi][ni][3] + bb.y;
            if (RES) {
                float2 r0 = *reinterpret_cast<const float2*>(&res[(size_t)row0 * NT + col]);
                float2 r1 = *reinterpret_cast<const float2*>(&res[(size_t)(row0 + 8) * NT + col]);
                o0.x += r0.x; o0.y += r0.y;
                o1.x += r1.x; o1.y += r1.y;
            }
            *reinterpret_cast<float2*>(&C[(size_t)row0 * NT + col]) = o0;
            *reinterpret_cast<float2*>(&C[(size_t)(row0 + 8) * NT + col]) = o1;
        }
    }
}

// ---------------- sampling v2: lane-specialized math + shfl broadcast ----------------
// Block = one bq, 8 warps = 8 heads. Lanes 0..3 compute point p's softmax weight,
// corner indices (pre-scaled by EMBED) and attention-premultiplied corner weights;
// broadcast via shfl; all 32 lanes do only the 16 gathers + 16 FMAs.
__global__ void __launch_bounds__(256)
sample_kernel(const float* __restrict__ refp, const float* __restrict__ oa,
              float* __restrict__ outp)
{
    const int lane = threadIdx.x & 31;
    const int h    = threadIdx.x >> 5;
    const int bq   = blockIdx.x;
    const int b    = bq / NQ;

    const float* oabase = oa + (size_t)bq * 96;

    // softmax over 4 points (lanes 0..3; higher lanes compute garbage, unused)
    float aw = 0.f, ox = 0.f, oy = 0.f;
    if (lane < 4) {
        aw = oabase[64 + h * 4 + lane];
        const float* op = oabase + h * 8 + 2 * lane;
        ox = op[0]; oy = op[1];
    }
    float m = fmaxf(aw, __shfl_xor_sync(0xffffffffu, aw, 1));
    m = fmaxf(m, __shfl_xor_sync(0xffffffffu, m, 2));
    float e = __expf(aw - m);
    float s = e + __shfl_xor_sync(0xffffffffu, e, 1);
    s = s + __shfl_xor_sync(0xffffffffu, s, 2);
    const float wp = e / s;   // valid on lanes 0..3

    const float rx = refp[(size_t)bq * 2 + 0];
    const float ry = refp[(size_t)bq * 2 + 1];

    // per-point geometry on lanes 0..3 (exact replication of reference arithmetic)
    int   i00 = 0, i01 = 0, i10 = 0, i11 = 0;
    float w00 = 0.f, w01 = 0.f, w10 = 0.f, w11 = 0.f;
    {
        float locx = rx + ox * (1.f / (float)SW);
        float locy = ry + oy * (1.f / (float)SH);
        float gx = 2.f * locx - 1.f;
        float gy = 2.f * locy - 1.f;
        float px = ((gx + 1.f) * (float)SW - 1.f) * 0.5f;
        float py = ((gy + 1.f) * (float)SH - 1.f) * 0.5f;
        float x0f = floorf(px), y0f = floorf(py);
        int   x0 = (int)x0f,    y0 = (int)y0f;
        float fx = px - x0f,    fy = py - y0f;

        const bool xv0 = (x0 >= 0)     && (x0 <= SW - 1);
        const bool xv1 = (x0 + 1 >= 0) && (x0 + 1 <= SW - 1);
        const bool yv0 = (y0 >= 0)     && (y0 <= SH - 1);
        const bool yv1 = (y0 + 1 >= 0) && (y0 + 1 <= SH - 1);

        int xc0 = min(max(x0, 0), SW - 1);
        int xc1 = min(max(x0 + 1, 0), SW - 1);
        int yc0 = min(max(y0, 0), SH - 1);
        int yc1 = min(max(y0 + 1, 0), SH - 1);

        w00 = (xv0 && yv0) ? wp * (1.f - fx) * (1.f - fy) : 0.f;
        w01 = (xv1 && yv0) ? wp * fx * (1.f - fy)         : 0.f;
        w10 = (xv0 && yv1) ? wp * (1.f - fx) * fy         : 0.f;
        w11 = (xv1 && yv1) ? wp * fx * fy                 : 0.f;

        i00 = (yc0 * SW + xc0) * EMBED;
        i01 = (yc0 * SW + xc1) * EMBED;
        i10 = (yc1 * SW + xc0) * EMBED;
        i11 = (yc1 * SW + xc1) * EMBED;
    }

    const float* vbase = g_v + (size_t)b * NV * EMBED + h * HEAD_DIM + lane;

    float acc = 0.f;
#pragma unroll
    for (int p = 0; p < POINTS; p++) {
        const int   j00 = __shfl_sync(0xffffffffu, i00, p);
        const int   j01 = __shfl_sync(0xffffffffu, i01, p);
        const int   j10 = __shfl_sync(0xffffffffu, i10, p);
        const int   j11 = __shfl_sync(0xffffffffu, i11, p);
        const float u00 = __shfl_sync(0xffffffffu, w00, p);
        const float u01 = __shfl_sync(0xffffffffu, w01, p);
        const float u10 = __shfl_sync(0xffffffffu, w10, p);
        const float u11 = __shfl_sync(0xffffffffu, w11, p);
        float v00 = vbase[j00];
        float v01 = vbase[j01];
        float v10 = vbase[j10];
        float v11 = vbase[j11];
        acc = fmaf(u00, v00, acc);
        acc = fmaf(u01, v01, acc);
        acc = fmaf(u10, v10, acc);
        acc = fmaf(u11, v11, acc);
    }

    outp[(size_t)bq * EMBED + h * HEAD_DIM + lane] = acc;
}

// ---------------- launch ----------------
extern "C" void kernel_launch(void* const* d_in, const int* in_sizes, int n_in,
                              void* d_out, int out_size)
{
    const float* query   = (const float*)d_in[0];
    const float* value   = (const float*)d_in[1];
    const float* refpts  = (const float*)d_in[2];
    const float* W_value = (const float*)d_in[4];
    const float* b_value = (const float*)d_in[5];
    const float* W_off   = (const float*)d_in[6];
    const float* b_off   = (const float*)d_in[7];
    const float* W_attn  = (const float*)d_in[8];
    const float* b_attn  = (const float*)d_in[9];
    const float* W_out   = (const float*)d_in[10];
    const float* b_out   = (const float*)d_in[11];
    float* out = (float*)d_out;

    float *pv, *poa, *ptmp, *pboa;
    __nv_bfloat16 *wv_h, *wv_l, *wo_h, *wo_l, *woa_h, *woa_l;
    cudaGetSymbolAddress((void**)&pv,    g_v);
    cudaGetSymbolAddress((void**)&poa,   g_oa);
    cudaGetSymbolAddress((void**)&ptmp,  g_tmp);
    cudaGetSymbolAddress((void**)&pboa,  g_boa);
    cudaGetSymbolAddress((void**)&wv_h,  g_Wv_hi);  cudaGetSymbolAddress((void**)&wv_l,  g_Wv_lo);
    cudaGetSymbolAddress((void**)&wo_h,  g_Wo_hi);  cudaGetSymbolAddress((void**)&wo_l,  g_Wo_lo);
    cudaGetSymbolAddress((void**)&woa_h, g_Woa_hi); cudaGetSymbolAddress((void**)&woa_l, g_Woa_lo);

    const int SMEM_256 = 2 * 128 * 144 + 2 * 256 * 144; // 110592
    const int SMEM_96  = 2 * 128 * 144 + 2 *  96 * 144; //  64512
    cudaFuncSetAttribute(mma_gemm_kernel<256, false>, cudaFuncAttributeMaxDynamicSharedMemorySize, SMEM_256);
    cudaFuncSetAttribute(mma_gemm_kernel<256, true >, cudaFuncAttributeMaxDynamicSharedMemorySize, SMEM_256);
    cudaFuncSetAttribute(mma_gemm_kernel< 96, false>, cudaFuncAttributeMaxDynamicSharedMemorySize, SMEM_96);

    // weight transpose + bf16 split
    convert_w_kernel<<<(256 * 256 + 255) / 256, 256>>>(W_value, wv_h, wv_l, 256);
    convert_w_kernel<<<(256 * 256 + 255) / 256, 256>>>(W_out,   wo_h, wo_l, 256);
    convert_oa_kernel<<<(96 * 256 + 255) / 256, 256>>>(W_off, b_off, W_attn, b_attn,
                                                       woa_h, woa_l, pboa);

    const int GRID = MROWS / 128; // 625

    // 1) v = value @ W_value + b_value
    mma_gemm_kernel<256, false><<<GRID, 256, SMEM_256>>>(value, wv_h, wv_l, b_value, nullptr, pv);
    // 2+3) [off|attn] = query @ [W_off|W_attn] + bias
    mma_gemm_kernel<96, false><<<GRID, 256, SMEM_96>>>(query, woa_h, woa_l, pboa, nullptr, poa);
    // 4) softmax + bilinear sample
    sample_kernel<<<BS * NQ, 256>>>(refpts, poa, ptmp);
    // 5) out = tmp @ W_out + b_out + query
    mma_gemm_kernel<256, true><<<GRID, 256, SMEM_256>>>(ptmp, wo_h, wo_l, b_out, query, out);
}

// round 5
// speedup vs baseline: 2.4058x; 1.0068x over previous
#include <cuda_runtime.h>
#include <cuda_bf16.h>
#include <math.h>
#include <stdint.h>

// ---------------- problem constants ----------------
#define BS      2
#define NQ      40000
#define NV      40000
#define EMBED   256
#define HEADS   8
#define POINTS  4
#define HEAD_DIM 32
#define SH      200
#define SW      200
#define MROWS   (BS * NQ)      // 80000

// ---------------- device scratch ----------------
__device__ float g_v   [(size_t)BS * NV * EMBED];
__device__ float g_oa  [(size_t)BS * NQ * 96];     // fused [off(64) | attn(32)]
__device__ float g_tmp [(size_t)BS * NQ * EMBED];
__device__ float g_boa [96];
// transposed + split weights: [N][K] bf16
__device__ __nv_bfloat16 g_Wv_hi [256 * 256], g_Wv_lo [256 * 256];
__device__ __nv_bfloat16 g_Wo_hi [256 * 256], g_Wo_lo [256 * 256];
__device__ __nv_bfloat16 g_Woa_hi[ 96 * 256], g_Woa_lo[ 96 * 256];

// ---------------- warp mma helper ----------------
__device__ __forceinline__ void mma_bf16(float* d, const uint32_t* a, const uint32_t* b) {
    asm volatile(
        "mma.sync.aligned.m16n8k16.row.col.f32.bf16.bf16.f32 "
        "{%0,%1,%2,%3}, {%4,%5,%6,%7}, {%8,%9}, {%0,%1,%2,%3};"
        : "+f"(d[0]), "+f"(d[1]), "+f"(d[2]), "+f"(d[3])
        : "r"(a[0]), "r"(a[1]), "r"(a[2]), "r"(a[3]), "r"(b[0]), "r"(b[1]));
}

// ---------------- weight transpose + bf16 split ----------------
__global__ void convert_w_kernel(const float* __restrict__ W,
                                 __nv_bfloat16* __restrict__ hi,
                                 __nv_bfloat16* __restrict__ lo, int N)
{
    int idx = blockIdx.x * 256 + threadIdx.x;
    if (idx >= N * 256) return;
    int n = idx >> 8, k = idx & 255;
    float v = W[k * N + n];
    __nv_bfloat16 h = __float2bfloat16(v);
    hi[idx] = h;
    lo[idx] = __float2bfloat16(v - __bfloat162float(h));
}

// combined [W_off | W_attn] transpose+split, plus combined bias
__global__ void convert_oa_kernel(const float* __restrict__ Woff, const float* __restrict__ boff,
                                  const float* __restrict__ Wattn, const float* __restrict__ battn,
                                  __nv_bfloat16* __restrict__ hi, __nv_bfloat16* __restrict__ lo,
                                  float* __restrict__ bcomb)
{
    int idx = blockIdx.x * 256 + threadIdx.x;
    if (idx >= 96 * 256) return;
    int n = idx >> 8, k = idx & 255;
    float v = (n < 64) ? Woff[k * 64 + n] : Wattn[k * 32 + (n - 64)];
    __nv_bfloat16 h = __float2bfloat16(v);
    hi[idx] = h;
    lo[idx] = __float2bfloat16(v - __bfloat162float(h));
    if (idx < 96) bcomb[idx] = (idx < 64) ? boff[idx] : battn[idx - 64];
}

// ---------------- split-bf16 HMMA GEMM v3 ----------------
// CTA tile: 128 x BN (BN = 128 or 96). gridDim.y splits total N.
// 8 warps, warp tile 64 x (BN/4). 2 CTAs per SM via __launch_bounds__(256,2).
template<int BN, bool RES>
__global__ void __launch_bounds__(256, 2)
mma_gemm_kernel(const float* __restrict__ A,
                const __nv_bfloat16* __restrict__ Bt_hi,
                const __nv_bfloat16* __restrict__ Bt_lo,
                const float* __restrict__ bias,
                const float* __restrict__ res,
                float* __restrict__ C, int ldC)
{
    constexpr int K = 256, BK = 64, BM = 128;
    constexpr int WM  = 2;
    constexpr int WN  = 4;
    constexpr int WTM = BM / WM;           // 64 rows per warp
    constexpr int WTN = BN / WN;           // 32 or 24 cols per warp
    constexpr int MT  = WTM / 16;          // 4
    constexpr int NTI = WTN / 8;           // 4 or 3
    constexpr int AST = 144;               // bytes per 64-bf16 row (128 + 16 pad)
    constexpr int A_H = 0;
    constexpr int A_L = BM * AST;
    constexpr int B_H = 2 * BM * AST;
    constexpr int B_L = B_H + BN * AST;

    extern __shared__ char sm[];

    const int tid  = threadIdx.x;
    const int wid  = tid >> 5;
    const int lane = tid & 31;
    const int g    = lane >> 2;
    const int c    = lane & 3;
    const int wm   = wid / WN;
    const int wn   = wid % WN;
    const int wmBase = wm * WTM;
    const int wnBase = wn * WTN;
    const int bm   = blockIdx.x;
    const int by   = blockIdx.y;
    const int nOff = by * BN;              // output-column offset of this CTA

    float acc[MT][NTI][4];
#pragma unroll
    for (int i = 0; i < MT; i++)
#pragma unroll
        for (int j = 0; j < NTI; j++)
#pragma unroll
            for (int q = 0; q < 4; q++) acc[i][j][q] = 0.f;

    const int aFragBase = A_H + (wmBase + g) * AST + c * 4;
    const int bFragBase = B_H + (wnBase + g) * AST + c * 4;

    for (int it = 0; it < K / BK; it++) {
        const int k0 = it * BK;
        // ---- fill A tile: 128 rows x 64 fp32 -> bf16 hi/lo ----
#pragma unroll
        for (int f = tid; f < BM * 32; f += 256) {
            const int r = f >> 5, c2 = f & 31;
            float2 a = *reinterpret_cast<const float2*>(
                &A[(size_t)(bm * BM + r) * K + k0 + c2 * 2]);
            __nv_bfloat16 h0 = __float2bfloat16(a.x);
            __nv_bfloat16 h1 = __float2bfloat16(a.y);
            __nv_bfloat16 l0 = __float2bfloat16(a.x - __bfloat162float(h0));
            __nv_bfloat16 l1 = __float2bfloat16(a.y - __bfloat162float(h1));
            __nv_bfloat162 vh; vh.x = h0; vh.y = h1;
            __nv_bfloat162 vl; vl.x = l0; vl.y = l1;
            *reinterpret_cast<__nv_bfloat162*>(sm + A_H + r * AST + c2 * 4) = vh;
            *reinterpret_cast<__nv_bfloat162*>(sm + A_L + r * AST + c2 * 4) = vl;
        }
        // ---- fill B tile: BN rows x 64 bf16 (pre-split) ----
#pragma unroll
        for (int f = tid; f < BN * 32; f += 256) {
            const int n = f >> 5, cu = f & 31;
            uint32_t hi = *reinterpret_cast<const uint32_t*>(&Bt_hi[(nOff + n) * K + k0 + cu * 2]);
            uint32_t lo = *reinterpret_cast<const uint32_t*>(&Bt_lo[(nOff + n) * K + k0 + cu * 2]);
            *reinterpret_cast<uint32_t*>(sm + B_H + n * AST + cu * 4) = hi;
            *reinterpret_cast<uint32_t*>(sm + B_L + n * AST + cu * 4) = lo;
        }
        __syncthreads();

#pragma unroll
        for (int ks = 0; ks < BK / 16; ks++) {
            const int kb = ks * 32;
            uint32_t af[MT][4], bh[NTI][2], bl[NTI][2];
            // B hi fragments
#pragma unroll
            for (int ni = 0; ni < NTI; ni++) {
                const int b0 = bFragBase + ni * 8 * AST + kb;
                bh[ni][0] = *reinterpret_cast<const uint32_t*>(sm + b0);
                bh[ni][1] = *reinterpret_cast<const uint32_t*>(sm + b0 + 16);
            }
            // A hi fragments
#pragma unroll
            for (int mi = 0; mi < MT; mi++) {
                const int a0 = aFragBase + mi * 16 * AST + kb;
                af[mi][0] = *reinterpret_cast<const uint32_t*>(sm + a0);
                af[mi][1] = *reinterpret_cast<const uint32_t*>(sm + a0 + 8 * AST);
                af[mi][2] = *reinterpret_cast<const uint32_t*>(sm + a0 + 16);
                af[mi][3] = *reinterpret_cast<const uint32_t*>(sm + a0 + 8 * AST + 16);
            }
            // pass 1: Ah x Bh
#pragma unroll
            for (int mi = 0; mi < MT; mi++)
#pragma unroll
                for (int ni = 0; ni < NTI; ni++)
                    mma_bf16(acc[mi][ni], af[mi], bh[ni]);
            // pass 2: Ah x Bl
#pragma unroll
            for (int ni = 0; ni < NTI; ni++) {
                const int b0 = (B_L - B_H) + bFragBase + ni * 8 * AST + kb;
                bl[ni][0] = *reinterpret_cast<const uint32_t*>(sm + b0);
                bl[ni][1] = *reinterpret_cast<const uint32_t*>(sm + b0 + 16);
            }
#pragma unroll
            for (int mi = 0; mi < MT; mi++)
#pragma unroll
                for (int ni = 0; ni < NTI; ni++)
                    mma_bf16(acc[mi][ni], af[mi], bl[ni]);
            // pass 3: Al x Bh (overwrite A frags with lo plane)
#pragma unroll
            for (int mi = 0; mi < MT; mi++) {
                const int a0 = (A_L - A_H) + aFragBase + mi * 16 * AST + kb;
                af[mi][0] = *reinterpret_cast<const uint32_t*>(sm + a0);
                af[mi][1] = *reinterpret_cast<const uint32_t*>(sm + a0 + 8 * AST);
                af[mi][2] = *reinterpret_cast<const uint32_t*>(sm + a0 + 16);
                af[mi][3] = *reinterpret_cast<const uint32_t*>(sm + a0 + 8 * AST + 16);
            }
#pragma unroll
            for (int mi = 0; mi < MT; mi++)
#pragma unroll
                for (int ni = 0; ni < NTI; ni++)
                    mma_bf16(acc[mi][ni], af[mi], bh[ni]);
        }
        __syncthreads();
    }

    // ---- epilogue ----
#pragma unroll
    for (int mi = 0; mi < MT; mi++) {
        const int row0 = bm * BM + wmBase + mi * 16 + g;
#pragma unroll
        for (int ni = 0; ni < NTI; ni++) {
            const int col = nOff + wnBase + ni * 8 + c * 2;
            float2 bb = *reinterpret_cast<const float2*>(&bias[col]);
            float2 o0, o1;
            o0.x = acc[mi][ni][0] + bb.x;
            o0.y = acc[mi][ni][1] + bb.y;
            o1.x = acc[mi][ni][2] + bb.x;
            o1.y = acc[mi][ni][3] + bb.y;
            if (RES) {
                float2 r0 = *reinterpret_cast<const float2*>(&res[(size_t)row0 * ldC + col]);
                float2 r1 = *reinterpret_cast<const float2*>(&res[(size_t)(row0 + 8) * ldC + col]);
                o0.x += r0.x; o0.y += r0.y;
                o1.x += r1.x; o1.y += r1.y;
            }
            *reinterpret_cast<float2*>(&C[(size_t)row0 * ldC + col]) = o0;
            *reinterpret_cast<float2*>(&C[(size_t)(row0 + 8) * ldC + col]) = o1;
        }
    }
}

// ---------------- sampling: lane-specialized math + shfl broadcast ----------------
__global__ void __launch_bounds__(256)
sample_kernel(const float* __restrict__ refp, const float* __restrict__ oa,
              float* __restrict__ outp)
{
    const int lane = threadIdx.x & 31;
    const int h    = threadIdx.x >> 5;
    const int bq   = blockIdx.x;
    const int b    = bq / NQ;

    const float* oabase = oa + (size_t)bq * 96;

    float aw = 0.f, ox = 0.f, oy = 0.f;
    if (lane < 4) {
        aw = oabase[64 + h * 4 + lane];
        const float* op = oabase + h * 8 + 2 * lane;
        ox = op[0]; oy = op[1];
    }
    float m = fmaxf(aw, __shfl_xor_sync(0xffffffffu, aw, 1));
    m = fmaxf(m, __shfl_xor_sync(0xffffffffu, m, 2));
    float e = __expf(aw - m);
    float s = e + __shfl_xor_sync(0xffffffffu, e, 1);
    s = s + __shfl_xor_sync(0xffffffffu, s, 2);
    const float wp = e / s;

    const float rx = refp[(size_t)bq * 2 + 0];
    const float ry = refp[(size_t)bq * 2 + 1];

    int   i00 = 0, i01 = 0, i10 = 0, i11 = 0;
    float w00 = 0.f, w01 = 0.f, w10 = 0.f, w11 = 0.f;
    {
        float locx = rx + ox * (1.f / (float)SW);
        float locy = ry + oy * (1.f / (float)SH);
        float gx = 2.f * locx - 1.f;
        float gy = 2.f * locy - 1.f;
        float px = ((gx + 1.f) * (float)SW - 1.f) * 0.5f;
        float py = ((gy + 1.f) * (float)SH - 1.f) * 0.5f;
        float x0f = floorf(px), y0f = floorf(py);
        int   x0 = (int)x0f,    y0 = (int)y0f;
        float fx = px - x0f,    fy = py - y0f;

        const bool xv0 = (x0 >= 0)     && (x0 <= SW - 1);
        const bool xv1 = (x0 + 1 >= 0) && (x0 + 1 <= SW - 1);
        const bool yv0 = (y0 >= 0)     && (y0 <= SH - 1);
        const bool yv1 = (y0 + 1 >= 0) && (y0 + 1 <= SH - 1);

        int xc0 = min(max(x0, 0), SW - 1);
        int xc1 = min(max(x0 + 1, 0), SW - 1);
        int yc0 = min(max(y0, 0), SH - 1);
        int yc1 = min(max(y0 + 1, 0), SH - 1);

        w00 = (xv0 && yv0) ? wp * (1.f - fx) * (1.f - fy) : 0.f;
        w01 = (xv1 && yv0) ? wp * fx * (1.f - fy)         : 0.f;
        w10 = (xv0 && yv1) ? wp * (1.f - fx) * fy         : 0.f;
        w11 = (xv1 && yv1) ? wp * fx * fy                 : 0.f;

        i00 = (yc0 * SW + xc0) * EMBED;
        i01 = (yc0 * SW + xc1) * EMBED;
        i10 = (yc1 * SW + xc0) * EMBED;
        i11 = (yc1 * SW + xc1) * EMBED;
    }

    const float* vbase = g_v + (size_t)b * NV * EMBED + h * HEAD_DIM + lane;

    float acc = 0.f;
#pragma unroll
    for (int p = 0; p < POINTS; p++) {
        const int   j00 = __shfl_sync(0xffffffffu, i00, p);
        const int   j01 = __shfl_sync(0xffffffffu, i01, p);
        const int   j10 = __shfl_sync(0xffffffffu, i10, p);
        const int   j11 = __shfl_sync(0xffffffffu, i11, p);
        const float u00 = __shfl_sync(0xffffffffu, w00, p);
        const float u01 = __shfl_sync(0xffffffffu, w01, p);
        const float u10 = __shfl_sync(0xffffffffu, w10, p);
        const float u11 = __shfl_sync(0xffffffffu, w11, p);
        float v00 = vbase[j00];
        float v01 = vbase[j01];
        float v10 = vbase[j10];
        float v11 = vbase[j11];
        acc = fmaf(u00, v00, acc);
        acc = fmaf(u01, v01, acc);
        acc = fmaf(u10, v10, acc);
        acc = fmaf(u11, v11, acc);
    }

    outp[(size_t)bq * EMBED + h * HEAD_DIM + lane] = acc;
}

// ---------------- launch ----------------
extern "C" void kernel_launch(void* const* d_in, const int* in_sizes, int n_in,
                              void* d_out, int out_size)
{
    const float* query   = (const float*)d_in[0];
    const float* value   = (const float*)d_in[1];
    const float* refpts  = (const float*)d_in[2];
    const float* W_value = (const float*)d_in[4];
    const float* b_value = (const float*)d_in[5];
    const float* W_off   = (const float*)d_in[6];
    const float* b_off   = (const float*)d_in[7];
    const float* W_attn  = (const float*)d_in[8];
    const float* b_attn  = (const float*)d_in[9];
    const float* W_out   = (const float*)d_in[10];
    const float* b_out   = (const float*)d_in[11];
    float* out = (float*)d_out;

    float *pv, *poa, *ptmp, *pboa;
    __nv_bfloat16 *wv_h, *wv_l, *wo_h, *wo_l, *woa_h, *woa_l;
    cudaGetSymbolAddress((void**)&pv,    g_v);
    cudaGetSymbolAddress((void**)&poa,   g_oa);
    cudaGetSymbolAddress((void**)&ptmp,  g_tmp);
    cudaGetSymbolAddress((void**)&pboa,  g_boa);
    cudaGetSymbolAddress((void**)&wv_h,  g_Wv_hi);  cudaGetSymbolAddress((void**)&wv_l,  g_Wv_lo);
    cudaGetSymbolAddress((void**)&wo_h,  g_Wo_hi);  cudaGetSymbolAddress((void**)&wo_l,  g_Wo_lo);
    cudaGetSymbolAddress((void**)&woa_h, g_Woa_hi); cudaGetSymbolAddress((void**)&woa_l, g_Woa_lo);

    const int SMEM_128 = (2 * 128 + 2 * 128) * 144; // 73728
    const int SMEM_96  = (2 * 128 + 2 *  96) * 144; // 64512
    cudaFuncSetAttribute(mma_gemm_kernel<128, false>, cudaFuncAttributeMaxDynamicSharedMemorySize, SMEM_128);
    cudaFuncSetAttribute(mma_gemm_kernel<128, true >, cudaFuncAttributeMaxDynamicSharedMemorySize, SMEM_128);
    cudaFuncSetAttribute(mma_gemm_kernel< 96, false>, cudaFuncAttributeMaxDynamicSharedMemorySize, SMEM_96);

    // weight transpose + bf16 split
    convert_w_kernel<<<(256 * 256 + 255) / 256, 256>>>(W_value, wv_h, wv_l, 256);
    convert_w_kernel<<<(256 * 256 + 255) / 256, 256>>>(W_out,   wo_h, wo_l, 256);
    convert_oa_kernel<<<(96 * 256 + 255) / 256, 256>>>(W_off, b_off, W_attn, b_attn,
                                                       woa_h, woa_l, pboa);

    const int GRID = MROWS / 128; // 625

    // 1) v = value @ W_value + b_value       (N=256 split into 2x128)
    mma_gemm_kernel<128, false><<<dim3(GRID, 2), 256, SMEM_128>>>(
        value, wv_h, wv_l, b_value, nullptr, pv, 256);
    // 2+3) [off|attn] = query @ [W_off|W_attn] + bias   (N=96)
    mma_gemm_kernel<96, false><<<dim3(GRID, 1), 256, SMEM_96>>>(
        query, woa_h, woa_l, pboa, nullptr, poa, 96);
    // 4) softmax + bilinear sample
    sample_kernel<<<BS * NQ, 256>>>(refpts, poa, ptmp);
    // 5) out = tmp @ W_out + b_out + query   (N=256 split into 2x128)
    mma_gemm_kernel<128, true><<<dim3(GRID, 2), 256, SMEM_128>>>(
        ptmp, wo_h, wo_l, b_out, query, out, 256);
}

// round 6
// speedup vs baseline: 2.7830x; 1.1568x over previous
#include <cuda_runtime.h>
#include <cuda_bf16.h>
#include <math.h>
#include <stdint.h>

// ---------------- problem constants ----------------
#define BS      2
#define NQ      40000
#define NV      40000
#define EMBED   256
#define HEADS   8
#define POINTS  4
#define HEAD_DIM 32
#define SH      200
#define SW      200
#define MROWS   (BS * NQ)      // 80000

// ---------------- device scratch ----------------
__device__ float g_v   [(size_t)BS * NV * EMBED];
__device__ float g_oa  [(size_t)BS * NQ * 96];     // fused [off(64) | attn(32)]
__device__ float g_tmp [(size_t)BS * NQ * EMBED];
__device__ float g_boa [96];
// transposed + split weights: [N][K] bf16
__device__ __nv_bfloat16 g_Wv_hi [256 * 256], g_Wv_lo [256 * 256];
__device__ __nv_bfloat16 g_Wo_hi [256 * 256], g_Wo_lo [256 * 256];
__device__ __nv_bfloat16 g_Woa_hi[ 96 * 256], g_Woa_lo[ 96 * 256];

// ---------------- warp mma / ldmatrix helpers ----------------
__device__ __forceinline__ void mma_bf16(float* d, const uint32_t* a, const uint32_t* b) {
    asm volatile(
        "mma.sync.aligned.m16n8k16.row.col.f32.bf16.bf16.f32 "
        "{%0,%1,%2,%3}, {%4,%5,%6,%7}, {%8,%9}, {%0,%1,%2,%3};"
        : "+f"(d[0]), "+f"(d[1]), "+f"(d[2]), "+f"(d[3])
        : "r"(a[0]), "r"(a[1]), "r"(a[2]), "r"(a[3]), "r"(b[0]), "r"(b[1]));
}
__device__ __forceinline__ void ldsm_x4(uint32_t& r0, uint32_t& r1, uint32_t& r2, uint32_t& r3,
                                        uint32_t addr) {
    asm volatile("ldmatrix.sync.aligned.m8n8.x4.shared.b16 {%0,%1,%2,%3}, [%4];"
                 : "=r"(r0), "=r"(r1), "=r"(r2), "=r"(r3) : "r"(addr));
}
__device__ __forceinline__ void ldsm_x2(uint32_t& r0, uint32_t& r1, uint32_t addr) {
    asm volatile("ldmatrix.sync.aligned.m8n8.x2.shared.b16 {%0,%1}, [%2];"
                 : "=r"(r0), "=r"(r1) : "r"(addr));
}

// ---------------- weight transpose + bf16 split ----------------
__global__ void convert_w_kernel(const float* __restrict__ W,
                                 __nv_bfloat16* __restrict__ hi,
                                 __nv_bfloat16* __restrict__ lo, int N)
{
    int idx = blockIdx.x * 256 + threadIdx.x;
    if (idx >= N * 256) return;
    int n = idx >> 8, k = idx & 255;
    float v = W[k * N + n];
    __nv_bfloat16 h = __float2bfloat16(v);
    hi[idx] = h;
    lo[idx] = __float2bfloat16(v - __bfloat162float(h));
}

// combined [W_off | W_attn] transpose+split, plus combined bias
__global__ void convert_oa_kernel(const float* __restrict__ Woff, const float* __restrict__ boff,
                                  const float* __restrict__ Wattn, const float* __restrict__ battn,
                                  __nv_bfloat16* __restrict__ hi, __nv_bfloat16* __restrict__ lo,
                                  float* __restrict__ bcomb)
{
    int idx = blockIdx.x * 256 + threadIdx.x;
    if (idx >= 96 * 256) return;
    int n = idx >> 8, k = idx & 255;
    float v = (n < 64) ? Woff[k * 64 + n] : Wattn[k * 32 + (n - 64)];
    __nv_bfloat16 h = __float2bfloat16(v);
    hi[idx] = h;
    lo[idx] = __float2bfloat16(v - __bfloat162float(h));
    if (idx < 96) bcomb[idx] = (idx < 64) ? boff[idx] : battn[idx - 64];
}

// ---------------- split-bf16 HMMA GEMM v4: ldmatrix fragment loads ----------------
// CTA tile: 128 x BN (BN = 128 or 96). gridDim.y splits total N.
// 8 warps, warp tile 64 x (BN/4). 2 CTAs per SM.
template<int BN, bool RES>
__global__ void __launch_bounds__(256, 2)
mma_gemm_kernel(const float* __restrict__ A,
                const __nv_bfloat16* __restrict__ Bt_hi,
                const __nv_bfloat16* __restrict__ Bt_lo,
                const float* __restrict__ bias,
                const float* __restrict__ res,
                float* __restrict__ C, int ldC)
{
    constexpr int K = 256, BK = 64, BM = 128;
    constexpr int WN  = 4;
    constexpr int WTM = 64;                // rows per warp
    constexpr int WTN = BN / WN;           // 32 or 24 cols per warp
    constexpr int MT  = WTM / 16;          // 4
    constexpr int NTI = WTN / 8;           // 4 or 3
    constexpr int NPAIR = NTI / 2;         // full x4 pairs
    constexpr int AST = 144;               // bytes per 64-bf16 row (128 + 16 pad)
    constexpr int A_H = 0;
    constexpr int A_L = BM * AST;
    constexpr int B_H = 2 * BM * AST;
    constexpr int B_L = B_H + BN * AST;

    extern __shared__ char sm[];

    const int tid  = threadIdx.x;
    const int wid  = tid >> 5;
    const int lane = tid & 31;
    const int g    = lane >> 2;
    const int c    = lane & 3;
    const int wm   = wid / WN;
    const int wn   = wid % WN;
    const int wmBase = wm * WTM;
    const int wnBase = wn * WTN;
    const int bm   = blockIdx.x;
    const int nOff = blockIdx.y * BN;

    float acc[MT][NTI][4];
#pragma unroll
    for (int i = 0; i < MT; i++)
#pragma unroll
        for (int j = 0; j < NTI; j++)
#pragma unroll
            for (int q = 0; q < 4; q++) acc[i][j][q] = 0.f;

    // ldmatrix lane-derived base addresses
    const int aRow = wmBase + (lane & 15);
    const int aKs  = (lane >> 4) * 16;
    const int bRow = wnBase + ((lane >> 4) << 3) + (lane & 7);
    const int bKs  = ((lane >> 3) & 1) * 16;
    const uint32_t aHiB = (uint32_t)__cvta_generic_to_shared(sm + A_H + aRow * AST + aKs);
    const uint32_t aLoB = aHiB + (uint32_t)(A_L - A_H);
    const uint32_t bHiB = (uint32_t)__cvta_generic_to_shared(sm + B_H + bRow * AST + bKs);
    const uint32_t bLoB = bHiB + (uint32_t)(B_L - B_H);

    for (int it = 0; it < K / BK; it++) {
        const int k0 = it * BK;
        // ---- fill A tile: 128 rows x 64 fp32 -> bf16 hi/lo (float4 loads) ----
#pragma unroll
        for (int f = tid; f < BM * 16; f += 256) {
            const int r = f >> 4, c4 = f & 15;
            float4 a = *reinterpret_cast<const float4*>(
                &A[(size_t)(bm * BM + r) * K + k0 + c4 * 4]);
            __nv_bfloat16 h0 = __float2bfloat16(a.x);
            __nv_bfloat16 h1 = __float2bfloat16(a.y);
            __nv_bfloat16 h2 = __float2bfloat16(a.z);
            __nv_bfloat16 h3 = __float2bfloat16(a.w);
            __nv_bfloat16 l0 = __float2bfloat16(a.x - __bfloat162float(h0));
            __nv_bfloat16 l1 = __float2bfloat16(a.y - __bfloat162float(h1));
            __nv_bfloat16 l2 = __float2bfloat16(a.z - __bfloat162float(h2));
            __nv_bfloat16 l3 = __float2bfloat16(a.w - __bfloat162float(h3));
            uint32_t hA = ((uint32_t)__bfloat16_as_ushort(h1) << 16) | __bfloat16_as_ushort(h0);
            uint32_t hB = ((uint32_t)__bfloat16_as_ushort(h3) << 16) | __bfloat16_as_ushort(h2);
            uint32_t lA = ((uint32_t)__bfloat16_as_ushort(l1) << 16) | __bfloat16_as_ushort(l0);
            uint32_t lB = ((uint32_t)__bfloat16_as_ushort(l3) << 16) | __bfloat16_as_ushort(l2);
            uint2 vh; vh.x = hA; vh.y = hB;
            uint2 vl; vl.x = lA; vl.y = lB;
            *reinterpret_cast<uint2*>(sm + A_H + r * AST + c4 * 8) = vh;
            *reinterpret_cast<uint2*>(sm + A_L + r * AST + c4 * 8) = vl;
        }
        // ---- fill B tile: BN rows x 64 bf16, 16B copies ----
#pragma unroll
        for (int f = tid; f < BN * 8; f += 256) {
            const int n = f >> 3, cu = f & 7;
            uint4 hi = *reinterpret_cast<const uint4*>(&Bt_hi[(nOff + n) * K + k0 + cu * 8]);
            uint4 lo = *reinterpret_cast<const uint4*>(&Bt_lo[(nOff + n) * K + k0 + cu * 8]);
            *reinterpret_cast<uint4*>(sm + B_H + n * AST + cu * 16) = hi;
            *reinterpret_cast<uint4*>(sm + B_L + n * AST + cu * 16) = lo;
        }
        __syncthreads();

#pragma unroll
        for (int ks = 0; ks < BK / 16; ks++) {
            const uint32_t kb = ks * 32;
            uint32_t af[MT][4], bh[NTI][2], bl[NTI][2];
            // B hi fragments: x4 per pair of n8 tiles (+ x2 tail)
#pragma unroll
            for (int p = 0; p < NPAIR; p++)
                ldsm_x4(bh[2*p][0], bh[2*p][1], bh[2*p+1][0], bh[2*p+1][1],
                        bHiB + (uint32_t)(p * 16 * AST) + kb);
            if (NTI & 1)
                ldsm_x2(bh[NTI-1][0], bh[NTI-1][1],
                        bHiB + (uint32_t)((NTI-1) * 8 * AST) + kb);
            // A hi fragments: x4 per 16-row tile
#pragma unroll
            for (int mi = 0; mi < MT; mi++)
                ldsm_x4(af[mi][0], af[mi][1], af[mi][2], af[mi][3],
                        aHiB + (uint32_t)(mi * 16 * AST) + kb);
            // pass 1: Ah x Bh
#pragma unroll
            for (int mi = 0; mi < MT; mi++)
#pragma unroll
                for (int ni = 0; ni < NTI; ni++)
                    mma_bf16(acc[mi][ni], af[mi], bh[ni]);
            // B lo fragments, pass 2: Ah x Bl
#pragma unroll
            for (int p = 0; p < NPAIR; p++)
                ldsm_x4(bl[2*p][0], bl[2*p][1], bl[2*p+1][0], bl[2*p+1][1],
                        bLoB + (uint32_t)(p * 16 * AST) + kb);
            if (NTI & 1)
                ldsm_x2(bl[NTI-1][0], bl[NTI-1][1],
                        bLoB + (uint32_t)((NTI-1) * 8 * AST) + kb);
#pragma unroll
            for (int mi = 0; mi < MT; mi++)
#pragma unroll
                for (int ni = 0; ni < NTI; ni++)
                    mma_bf16(acc[mi][ni], af[mi], bl[ni]);
            // A lo fragments (overwrite), pass 3: Al x Bh
#pragma unroll
            for (int mi = 0; mi < MT; mi++)
                ldsm_x4(af[mi][0], af[mi][1], af[mi][2], af[mi][3],
                        aLoB + (uint32_t)(mi * 16 * AST) + kb);
#pragma unroll
            for (int mi = 0; mi < MT; mi++)
#pragma unroll
                for (int ni = 0; ni < NTI; ni++)
                    mma_bf16(acc[mi][ni], af[mi], bh[ni]);
        }
        __syncthreads();
    }

    // ---- epilogue ----
#pragma unroll
    for (int mi = 0; mi < MT; mi++) {
        const int row0 = bm * BM + wmBase + mi * 16 + g;
#pragma unroll
        for (int ni = 0; ni < NTI; ni++) {
            const int col = nOff + wnBase + ni * 8 + c * 2;
            float2 bb = *reinterpret_cast<const float2*>(&bias[col]);
            float2 o0, o1;
            o0.x = acc[mi][ni][0] + bb.x;
            o0.y = acc[mi][ni][1] + bb.y;
            o1.x = acc[mi][ni][2] + bb.x;
            o1.y = acc[mi][ni][3] + bb.y;
            if (RES) {
                float2 r0 = *reinterpret_cast<const float2*>(&res[(size_t)row0 * ldC + col]);
                float2 r1 = *reinterpret_cast<const float2*>(&res[(size_t)(row0 + 8) * ldC + col]);
                o0.x += r0.x; o0.y += r0.y;
                o1.x += r1.x; o1.y += r1.y;
            }
            *reinterpret_cast<float2*>(&C[(size_t)row0 * ldC + col]) = o0;
            *reinterpret_cast<float2*>(&C[(size_t)(row0 + 8) * ldC + col]) = o1;
        }
    }
}

// ---------------- sampling: lane-specialized math + shfl broadcast ----------------
__global__ void __launch_bounds__(256)
sample_kernel(const float* __restrict__ refp, const float* __restrict__ oa,
              float* __restrict__ outp)
{
    const int lane = threadIdx.x & 31;
    const int h    = threadIdx.x >> 5;
    const int bq   = blockIdx.x;
    const int b    = bq / NQ;

    const float* oabase = oa + (size_t)bq * 96;

    float aw = 0.f, ox = 0.f, oy = 0.f;
    if (lane < 4) {
        aw = oabase[64 + h * 4 + lane];
        const float* op = oabase + h * 8 + 2 * lane;
        ox = op[0]; oy = op[1];
    }
    float m = fmaxf(aw, __shfl_xor_sync(0xffffffffu, aw, 1));
    m = fmaxf(m, __shfl_xor_sync(0xffffffffu, m, 2));
    float e = __expf(aw - m);
    float s = e + __shfl_xor_sync(0xffffffffu, e, 1);
    s = s + __shfl_xor_sync(0xffffffffu, s, 2);
    const float wp = e / s;

    const float rx = refp[(size_t)bq * 2 + 0];
    const float ry = refp[(size_t)bq * 2 + 1];

    int   i00 = 0, i01 = 0, i10 = 0, i11 = 0;
    float w00 = 0.f, w01 = 0.f, w10 = 0.f, w11 = 0.f;
    {
        float locx = rx + ox * (1.f / (float)SW);
        float locy = ry + oy * (1.f / (float)SH);
        float gx = 2.f * locx - 1.f;
        float gy = 2.f * locy - 1.f;
        float px = ((gx + 1.f) * (float)SW - 1.f) * 0.5f;
        float py = ((gy + 1.f) * (float)SH - 1.f) * 0.5f;
        float x0f = floorf(px), y0f = floorf(py);
        int   x0 = (int)x0f,    y0 = (int)y0f;
        float fx = px - x0f,    fy = py - y0f;

        const bool xv0 = (x0 >= 0)     && (x0 <= SW - 1);
        const bool xv1 = (x0 + 1 >= 0) && (x0 + 1 <= SW - 1);
        const bool yv0 = (y0 >= 0)     && (y0 <= SH - 1);
        const bool yv1 = (y0 + 1 >= 0) && (y0 + 1 <= SH - 1);

        int xc0 = min(max(x0, 0), SW - 1);
        int xc1 = min(max(x0 + 1, 0), SW - 1);
        int yc0 = min(max(y0, 0), SH - 1);
        int yc1 = min(max(y0 + 1, 0), SH - 1);

        w00 = (xv0 && yv0) ? wp * (1.f - fx) * (1.f - fy) : 0.f;
        w01 = (xv1 && yv0) ? wp * fx * (1.f - fy)         : 0.f;
        w10 = (xv0 && yv1) ? wp * (1.f - fx) * fy         : 0.f;
        w11 = (xv1 && yv1) ? wp * fx * fy                 : 0.f;

        i00 = (yc0 * SW + xc0) * EMBED;
        i01 = (yc0 * SW + xc1) * EMBED;
        i10 = (yc1 * SW + xc0) * EMBED;
        i11 = (yc1 * SW + xc1) * EMBED;
    }

    const float* vbase = g_v + (size_t)b * NV * EMBED + h * HEAD_DIM + lane;

    float acc = 0.f;
#pragma unroll
    for (int p = 0; p < POINTS; p++) {
        const int   j00 = __shfl_sync(0xffffffffu, i00, p);
        const int   j01 = __shfl_sync(0xffffffffu, i01, p);
        const int   j10 = __shfl_sync(0xffffffffu, i10, p);
        const int   j11 = __shfl_sync(0xffffffffu, i11, p);
        const float u00 = __shfl_sync(0xffffffffu, w00, p);
        const float u01 = __shfl_sync(0xffffffffu, w01, p);
        const float u10 = __shfl_sync(0xffffffffu, w10, p);
        const float u11 = __shfl_sync(0xffffffffu, w11, p);
        float v00 = vbase[j00];
        float v01 = vbase[j01];
        float v10 = vbase[j10];
        float v11 = vbase[j11];
        acc = fmaf(u00, v00, acc);
        acc = fmaf(u01, v01, acc);
        acc = fmaf(u10, v10, acc);
        acc = fmaf(u11, v11, acc);
    }

    outp[(size_t)bq * EMBED + h * HEAD_DIM + lane] = acc;
}

// ---------------- launch ----------------
extern "C" void kernel_launch(void* const* d_in, const int* in_sizes, int n_in,
                              void* d_out, int out_size)
{
    const float* query   = (const float*)d_in[0];
    const float* value   = (const float*)d_in[1];
    const float* refpts  = (const float*)d_in[2];
    const float* W_value = (const float*)d_in[4];
    const float* b_value = (const float*)d_in[5];
    const float* W_off   = (const float*)d_in[6];
    const float* b_off   = (const float*)d_in[7];
    const float* W_attn  = (const float*)d_in[8];
    const float* b_attn  = (const float*)d_in[9];
    const float* W_out   = (const float*)d_in[10];
    const float* b_out   = (const float*)d_in[11];
    float* out = (float*)d_out;

    float *pv, *poa, *ptmp, *pboa;
    __nv_bfloat16 *wv_h, *wv_l, *wo_h, *wo_l, *woa_h, *woa_l;
    cudaGetSymbolAddress((void**)&pv,    g_v);
    cudaGetSymbolAddress((void**)&poa,   g_oa);
    cudaGetSymbolAddress((void**)&ptmp,  g_tmp);
    cudaGetSymbolAddress((void**)&pboa,  g_boa);
    cudaGetSymbolAddress((void**)&wv_h,  g_Wv_hi);  cudaGetSymbolAddress((void**)&wv_l,  g_Wv_lo);
    cudaGetSymbolAddress((void**)&wo_h,  g_Wo_hi);  cudaGetSymbolAddress((void**)&wo_l,  g_Wo_lo);
    cudaGetSymbolAddress((void**)&woa_h, g_Woa_hi); cudaGetSymbolAddress((void**)&woa_l, g_Woa_lo);

    const int SMEM_128 = (2 * 128 + 2 * 128) * 144; // 73728
    const int SMEM_96  = (2 * 128 + 2 *  96) * 144; // 64512
    cudaFuncSetAttribute(mma_gemm_kernel<128, false>, cudaFuncAttributeMaxDynamicSharedMemorySize, SMEM_128);
    cudaFuncSetAttribute(mma_gemm_kernel<128, true >, cudaFuncAttributeMaxDynamicSharedMemorySize, SMEM_128);
    cudaFuncSetAttribute(mma_gemm_kernel< 96, false>, cudaFuncAttributeMaxDynamicSharedMemorySize, SMEM_96);

    // weight transpose + bf16 split
    convert_w_kernel<<<(256 * 256 + 255) / 256, 256>>>(W_value, wv_h, wv_l, 256);
    convert_w_kernel<<<(256 * 256 + 255) / 256, 256>>>(W_out,   wo_h, wo_l, 256);
    convert_oa_kernel<<<(96 * 256 + 255) / 256, 256>>>(W_off, b_off, W_attn, b_attn,
                                                       woa_h, woa_l, pboa);

    const int GRID = MROWS / 128; // 625

    // 1) v = value @ W_value + b_value       (N=256 split into 2x128)
    mma_gemm_kernel<128, false><<<dim3(GRID, 2), 256, SMEM_128>>>(
        value, wv_h, wv_l, b_value, nullptr, pv, 256);
    // 2+3) [off|attn] = query @ [W_off|W_attn] + bias   (N=96)
    mma_gemm_kernel<96, false><<<dim3(GRID, 1), 256, SMEM_96>>>(
        query, woa_h, woa_l, pboa, nullptr, poa, 96);
    // 4) softmax + bilinear sample
    sample_kernel<<<BS * NQ, 256>>>(refpts, poa, ptmp);
    // 5) out = tmp @ W_out + b_out + query   (N=256 split into 2x128)
    mma_gemm_kernel<128, true><<<dim3(GRID, 2), 256, SMEM_128>>>(
        ptmp, wo_h, wo_l, b_out, query, out, 256);
}